// round 2
// baseline (speedup 1.0000x reference)
#include <cuda_runtime.h>
#include <math.h>

#define MAXN 131072
#define DIM  512

// Scratch (no allocations allowed in kernel_launch)
__device__ float g_dot[MAXN];     // f_j . attn_w
__device__ float g_scores[MAXN];  // windowed-mean scores
__device__ float g_gw[MAXN];      // g_j = sum_{i in win(j)} w_i / c_i
__device__ float g_pm[2048];      // per-block partial max
__device__ float g_ps[2048];      // per-block partial sumexp
__device__ float g_M, g_S;        // global softmax stats

// ---------------- K1: per-row dot product, one warp per row ----------------
__global__ void k_dot(const float* __restrict__ f, const float* __restrict__ w, int n) {
    int warp = threadIdx.x >> 5;
    int lane = threadIdx.x & 31;
    int row  = blockIdx.x * (blockDim.x >> 5) + warp;
    if (row >= n) return;
    const float4* fr = (const float4*)f + (size_t)row * (DIM / 4);
    const float4* wv = (const float4*)w;
    float s = 0.f;
#pragma unroll
    for (int i = 0; i < DIM / 128; i++) {
        float4 a = fr[lane + 32 * i];
        float4 b = wv[lane + 32 * i];
        s += a.x * b.x + a.y * b.y + a.z * b.z + a.w * b.w;
    }
#pragma unroll
    for (int o = 16; o; o >>= 1) s += __shfl_down_sync(0xffffffffu, s, o);
    if (lane == 0) g_dot[row] = s;
}

// ------- K2: windowed-mean scores + per-block online-softmax partials -------
__global__ void k_scores(int n, const int* __restrict__ kptr, const float* __restrict__ bptr) {
    int i = blockIdx.x * blockDim.x + threadIdx.x;
    int t = threadIdx.x;
    float val = -3.0e38f;
    if (i < n) {
        int k  = *kptr;
        int lo = max(i - k, 0);
        int hi = min(i + k, n - 1);
        float s = 0.f;
        for (int j = lo; j <= hi; j++) s += g_dot[j];
        val = s / (float)(hi - lo + 1) + bptr[0];
        g_scores[i] = val;
    }
    __shared__ float sm[256];
    __shared__ float ss[256];
    sm[t] = val;
    __syncthreads();
    for (int o = blockDim.x >> 1; o; o >>= 1) {
        if (t < o) sm[t] = fmaxf(sm[t], sm[t + o]);
        __syncthreads();
    }
    float bmax = sm[0];
    __syncthreads();
    ss[t] = (i < n) ? expf(val - bmax) : 0.f;
    __syncthreads();
    for (int o = blockDim.x >> 1; o; o >>= 1) {
        if (t < o) ss[t] += ss[t + o];
        __syncthreads();
    }
    if (t == 0) { g_pm[blockIdx.x] = bmax; g_ps[blockIdx.x] = ss[0]; }
}

// ---------------- K3: merge partials (single block) ----------------
__global__ void k_merge(int nb) {
    __shared__ float sm[1024];
    __shared__ float ss[1024];
    int t = threadIdx.x;
    float m = -3.0e38f, s = 0.f;
    for (int i = t; i < nb; i += blockDim.x) {
        float mi = g_pm[i], si = g_ps[i];
        float nm = fmaxf(m, mi);
        s = s * expf(m - nm) + si * expf(mi - nm);
        m = nm;
    }
    sm[t] = m; ss[t] = s;
    __syncthreads();
    for (int o = blockDim.x >> 1; o; o >>= 1) {
        if (t < o) {
            float m2 = sm[t + o], s2 = ss[t + o];
            float nm = fmaxf(sm[t], m2);
            ss[t] = ss[t] * expf(sm[t] - nm) + s2 * expf(m2 - nm);
            sm[t] = nm;
        }
        __syncthreads();
    }
    if (t == 0) { g_M = sm[0]; g_S = ss[0]; }
}

// --------- K4: w_i to output; g_j = sum_{i in win(j)} w_i/c_i; zero bag ---------
__global__ void k_weights(float* __restrict__ out, int n, const int* __restrict__ kptr) {
    int i = blockIdx.x * blockDim.x + threadIdx.x;
    // Zero the FULL bag region out[0:DIM]. blockDim=256, so blocks 0 and 1
    // together cover all 512 entries. (Previous bug: only block 0 -> 256 zeroed,
    // causing atomicAdd accumulation across graph replays.)
    if (i < DIM) out[i] = 0.f;
    if (i >= n) return;
    int k = *kptr;
    float M = g_M;
    float invS = 1.f / g_S;
    float wi = expf(g_scores[i] - M) * invS;
    out[DIM + i] = wi;
    int lo = max(i - k, 0);
    int hi = min(i + k, n - 1);
    float g = 0.f;
    for (int j = lo; j <= hi; j++) {
        int loj = max(j - k, 0);
        int hij = min(j + k, n - 1);
        float cj = (float)(hij - loj + 1);
        g += expf(g_scores[j] - M) / cj;
    }
    g_gw[i] = g * invS;
}

// ---------------- K5: bag[c] = sum_j g_j * f[j][c] ----------------
__global__ void k_bag(const float* __restrict__ f, float* __restrict__ out, int n) {
    int c  = threadIdx.x;                     // 512 threads = 512 columns
    int nb = gridDim.x;
    int chunk = (n + nb - 1) / nb;
    int j0 = blockIdx.x * chunk;
    int j1 = min(j0 + chunk, n);
    float acc = 0.f;
    int j = j0;
#pragma unroll 1
    for (; j + 3 < j1; j += 4) {
        float g0 = g_gw[j + 0], g1 = g_gw[j + 1], g2 = g_gw[j + 2], g3 = g_gw[j + 3];
        float f0 = f[(size_t)(j + 0) * DIM + c];
        float f1 = f[(size_t)(j + 1) * DIM + c];
        float f2 = f[(size_t)(j + 2) * DIM + c];
        float f3 = f[(size_t)(j + 3) * DIM + c];
        acc += g0 * f0 + g1 * f1 + g2 * f2 + g3 * f3;
    }
    for (; j < j1; j++) acc += g_gw[j] * f[(size_t)j * DIM + c];
    atomicAdd(&out[c], acc);
}

extern "C" void kernel_launch(void* const* d_in, const int* in_sizes, int n_in,
                              void* d_out, int out_size) {
    const float* features = (const float*)d_in[0];
    const float* attn_w   = (const float*)d_in[1];
    const float* attn_b   = (const float*)d_in[2];
    const int*   kptr     = (const int*)d_in[3];
    float* out = (float*)d_out;

    int d = in_sizes[1];            // 512
    int n = in_sizes[0] / d;        // 100000
    (void)n_in; (void)out_size;

    // K1: dots — 8 warps/block, 1 warp/row
    {
        int rows_per_block = 8;
        int nb = (n + rows_per_block - 1) / rows_per_block;
        k_dot<<<nb, 256>>>(features, attn_w, n);
    }
    // K2: scores + softmax partials
    int nb2 = (n + 255) / 256;
    k_scores<<<nb2, 256>>>(n, kptr, attn_b);
    // K3: merge
    k_merge<<<1, 1024>>>(nb2);
    // K4: weights out + g_j + zero bag
    k_weights<<<nb2, 256>>>(out, n, kptr);
    // K5: weighted column sum
    k_bag<<<592, DIM>>>(features, out, n);
}

// round 4
// speedup vs baseline: 1.0400x; 1.0400x over previous
#include <cuda_runtime.h>
#include <math.h>

#define MAXN 131072
#define DIM  512

// Scratch (no allocations allowed in kernel_launch)
__device__ float g_dot[MAXN];     // f_j . attn_w
__device__ float g_scores[MAXN];  // windowed-mean scores
__device__ float g_gw[MAXN];      // g_j = sum_{i in win(j)} w_i / c_i
__device__ float g_pm[2048];      // per-block partial max
__device__ float g_ps[2048];      // per-block partial sumexp
__device__ float g_M, g_S;        // global softmax stats

// ---------------- K1: per-row dot product, one warp per row ----------------
__global__ void k_dot(const float* __restrict__ f, const float* __restrict__ w, int n) {
    int warp = threadIdx.x >> 5;
    int lane = threadIdx.x & 31;
    int row  = blockIdx.x * (blockDim.x >> 5) + warp;
    if (row >= n) return;
    const float4* fr = (const float4*)f + (size_t)row * (DIM / 4);
    const float4* wv = (const float4*)w;
    float s = 0.f;
#pragma unroll
    for (int i = 0; i < DIM / 128; i++) {
        float4 a = __ldcs(&fr[lane + 32 * i]);   // streaming: read-once data
        float4 b = __ldg(&wv[lane + 32 * i]);    // hot: keep in L1
        s += a.x * b.x + a.y * b.y + a.z * b.z + a.w * b.w;
    }
#pragma unroll
    for (int o = 16; o; o >>= 1) s += __shfl_down_sync(0xffffffffu, s, o);
    if (lane == 0) g_dot[row] = s;
}

// ------- K2: windowed-mean scores + per-block online-softmax partials -------
__global__ void k_scores(int n, const int* __restrict__ kptr, const float* __restrict__ bptr) {
    int i = blockIdx.x * blockDim.x + threadIdx.x;
    int t = threadIdx.x;
    int lane = t & 31, warp = t >> 5;
    float val = -3.0e38f;
    if (i < n) {
        int k  = *kptr;
        int lo = max(i - k, 0);
        int hi = min(i + k, n - 1);
        float s = 0.f;
        for (int j = lo; j <= hi; j++) s += g_dot[j];
        val = s / (float)(hi - lo + 1) + bptr[0];
        g_scores[i] = val;
    }
    // warp-level max
    float m = val;
#pragma unroll
    for (int o = 16; o; o >>= 1) m = fmaxf(m, __shfl_xor_sync(0xffffffffu, m, o));
    __shared__ float wm[8];
    if (lane == 0) wm[warp] = m;
    __syncthreads();
    float bmax = wm[0];
#pragma unroll
    for (int q = 1; q < 8; q++) bmax = fmaxf(bmax, wm[q]);
    // warp-level sum of exp
    float e = (i < n) ? __expf(val - bmax) : 0.f;
#pragma unroll
    for (int o = 16; o; o >>= 1) e += __shfl_xor_sync(0xffffffffu, e, o);
    __shared__ float ws[8];
    if (lane == 0) ws[warp] = e;
    __syncthreads();
    if (t == 0) {
        float s = ws[0];
#pragma unroll
        for (int q = 1; q < 8; q++) s += ws[q];
        g_pm[blockIdx.x] = bmax;
        g_ps[blockIdx.x] = s;
    }
}

// ---------------- K3: merge partials (single block) ----------------
__global__ void k_merge(int nb) {
    __shared__ float sm[1024];
    __shared__ float ss[1024];
    int t = threadIdx.x;
    float m = -3.0e38f, s = 0.f;
    for (int i = t; i < nb; i += blockDim.x) {
        float mi = g_pm[i], si = g_ps[i];
        float nm = fmaxf(m, mi);
        s = s * __expf(m - nm) + si * __expf(mi - nm);
        m = nm;
    }
    sm[t] = m; ss[t] = s;
    __syncthreads();
    for (int o = blockDim.x >> 1; o; o >>= 1) {
        if (t < o) {
            float m2 = sm[t + o], s2 = ss[t + o];
            float nm = fmaxf(sm[t], m2);
            ss[t] = ss[t] * __expf(sm[t] - nm) + s2 * __expf(m2 - nm);
            sm[t] = nm;
        }
        __syncthreads();
    }
    if (t == 0) { g_M = sm[0]; g_S = ss[0]; }
}

// --------- K4: w_i to output; g_j = sum_{i in win(j)} w_i/c_i; zero bag ---------
__global__ void k_weights(float* __restrict__ out, int n, const int* __restrict__ kptr) {
    int i = blockIdx.x * blockDim.x + threadIdx.x;
    // Zero the FULL bag region out[0:DIM] (blocks 0 and 1 cover all 512).
    if (i < DIM) out[i] = 0.f;
    if (i >= n) return;
    int k = *kptr;
    float M = g_M;
    float invS = 1.f / g_S;
    float wi = __expf(g_scores[i] - M) * invS;
    out[DIM + i] = wi;
    int lo = max(i - k, 0);
    int hi = min(i + k, n - 1);
    float g = 0.f;
    for (int j = lo; j <= hi; j++) {
        int loj = max(j - k, 0);
        int hij = min(j + k, n - 1);
        float cj = (float)(hij - loj + 1);
        g += __expf(g_scores[j] - M) * (1.f / cj);
    }
    g_gw[i] = g * invS;
}

// ---------------- K5: bag[c] = sum_j g_j * f[j][c] ----------------
__global__ void k_bag(const float* __restrict__ f, float* __restrict__ out, int n) {
    int c  = threadIdx.x;                     // 512 threads = 512 columns
    int nb = gridDim.x;
    int chunk = (n + nb - 1) / nb;
    int j0 = blockIdx.x * chunk;
    int j1 = min(j0 + chunk, n);
    float acc = 0.f;
    int j = j0;
#pragma unroll 1
    for (; j + 3 < j1; j += 4) {
        float g0 = g_gw[j + 0], g1 = g_gw[j + 1], g2 = g_gw[j + 2], g3 = g_gw[j + 3];
        float f0 = __ldcs(&f[(size_t)(j + 0) * DIM + c]);
        float f1 = __ldcs(&f[(size_t)(j + 1) * DIM + c]);
        float f2 = __ldcs(&f[(size_t)(j + 2) * DIM + c]);
        float f3 = __ldcs(&f[(size_t)(j + 3) * DIM + c]);
        acc += g0 * f0 + g1 * f1 + g2 * f2 + g3 * f3;
    }
    for (; j < j1; j++) acc += g_gw[j] * __ldcs(&f[(size_t)j * DIM + c]);
    atomicAdd(&out[c], acc);
}

extern "C" void kernel_launch(void* const* d_in, const int* in_sizes, int n_in,
                              void* d_out, int out_size) {
    const float* features = (const float*)d_in[0];
    const float* attn_w   = (const float*)d_in[1];
    const float* attn_b   = (const float*)d_in[2];
    const int*   kptr     = (const int*)d_in[3];
    float* out = (float*)d_out;

    int d = in_sizes[1];            // 512
    int n = in_sizes[0] / d;        // 100000
    (void)n_in; (void)out_size;

    // K1: dots — 8 warps/block, 1 warp/row
    {
        int rows_per_block = 8;
        int nb = (n + rows_per_block - 1) / rows_per_block;
        k_dot<<<nb, 256>>>(features, attn_w, n);
    }
    // K2: scores + softmax partials
    int nb2 = (n + 255) / 256;
    k_scores<<<nb2, 256>>>(n, kptr, attn_b);
    // K3: merge
    k_merge<<<1, 1024>>>(nb2);
    // K4: weights out + g_j + zero bag
    k_weights<<<nb2, 256>>>(out, n, kptr);
    // K5: weighted column sum
    k_bag<<<592, DIM>>>(features, out, n);
}